// round 14
// baseline (speedup 1.0000x reference)
#include <cuda_runtime.h>
#include <cuda_fp16.h>
#include <cstdint>

#define NNODES 10000
#define NEDGES 160000
#define INCH   256
#define HID    512
#define LDA    1024          // activation staging row stride (fp16 elems)

// weight regions in g_wh/g_wl (elems): transposed [512, K] per GEMM
#define WOFF_IN    0
#define WOFF_MSG0  (512 * 256)
#define WOFF_UPDH0 (WOFF_MSG0  + 512 * 512)
#define WOFF_UPDA0 (WOFF_UPDH0 + 512 * 512)
#define WOFF_MSG1  (WOFF_UPDA0 + 512 * 512)
#define WOFF_UPDH1 (WOFF_MSG1  + 512 * 512)
#define WOFF_UPDA1 (WOFF_UPDH1 + 512 * 512)
#define WTOTAL     (WOFF_UPDA1 + 512 * 512)

// ---------------- device scratch (referenced ONLY from device code) ----------------
__device__ __half g_act[2 * NNODES * LDA];
__device__ __half g_m  [NNODES * HID];
__device__ float  g_pacc[NNODES * HID];        // fp32 partial for split update GEMM
__device__ __half g_wh [WTOTAL];
__device__ __half g_wl [WTOTAL];
__device__ int   g_deg   [NNODES];
__device__ int   g_rowptr[NNODES + 1];
__device__ int   g_cursor[NNODES];
__device__ int   g_col   [NEDGES];
__device__ int   g_is64;

__device__ __forceinline__ uint32_t smem_u32(const void* p) {
    uint32_t a;
    asm("{ .reg .u64 t; cvta.to.shared.u64 t, %1; cvt.u32.u64 %0, t; }" : "=r"(a) : "l"(p));
    return a;
}
#define SWZ128(o) ((o) ^ (((o) >> 3) & 0x70))

#define LDSM4(r, addr)                                                        \
    asm volatile("ldmatrix.sync.aligned.m8n8.x4.shared.b16 {%0,%1,%2,%3}, [%4];" \
        : "=r"((r)[0]), "=r"((r)[1]), "=r"((r)[2]), "=r"((r)[3]) : "r"(addr))

#define MMA_F16(d, a, b)                                                      \
    asm volatile("mma.sync.aligned.m16n8k16.row.col.f32.f16.f16.f32 "         \
        "{%0,%1,%2,%3}, {%4,%5,%6,%7}, {%8,%9}, {%0,%1,%2,%3};"               \
        : "+f"((d)[0]), "+f"((d)[1]), "+f"((d)[2]), "+f"((d)[3])              \
        : "r"((a)[0]), "r"((a)[1]), "r"((a)[2]), "r"((a)[3]),                 \
          "r"((b)[0]), "r"((b)[1]))

#define CP16(sa, gp)  asm volatile("cp.async.cg.shared.global [%0], [%1], 16;" :: "r"(sa), "l"(gp))
#define CP_COMMIT()   asm volatile("cp.async.commit_group;" ::: "memory")
#define CP_WAIT0()    asm volatile("cp.async.wait_group 0;" ::: "memory")
#define CP_WAIT1()    asm volatile("cp.async.wait_group 1;" ::: "memory")

// ---------------- edge index (dtype-robust) ----------------
__device__ __forceinline__ int edge_at(const void* p, int which, int e) {
    long long v;
    if (g_is64) v = ((const long long*)p)[(size_t)which * NEDGES + e];
    else        v = ((const int*)p)[(size_t)which * NEDGES + e];
    int iv = (int)v;
    if (iv < 0) iv = 0;
    if (iv >= NNODES) iv = NNODES - 1;
    return iv;
}

__global__ void sniff_kernel(const unsigned int* __restrict__ w) {
    __shared__ int nz;
    if (threadIdx.x == 0) nz = 0;
    __syncthreads();
    int c = 0;
    for (int i = threadIdx.x; i < 2048; i += blockDim.x)
        if (w[2 * i + 1] != 0u) c++;
    if (c) atomicAdd(&nz, c);
    __syncthreads();
    if (threadIdx.x == 0) g_is64 = (nz == 0) ? 1 : 0;
}

// ---------------- CSR build ----------------
__global__ void zero_deg_kernel() {
    int i = blockIdx.x * blockDim.x + threadIdx.x;
    if (i < NNODES) g_deg[i] = 0;
}
__global__ void hist_kernel(const void* __restrict__ eidx, int nE) {
    int e = blockIdx.x * blockDim.x + threadIdx.x;
    if (e < nE) atomicAdd(&g_deg[edge_at(eidx, 1, e)], 1);
}
__global__ void scan_kernel(int n, int nE) {
    __shared__ int wsum[32];
    int tid = threadIdx.x;                 // 1024 threads
    const int CH = (n + 1023) / 1024;
    int start = tid * CH;
    int s = 0;
    for (int i = 0; i < CH; i++) {
        int idx = start + i;
        if (idx < n) s += g_deg[idx];
    }
    int lane = tid & 31, warp = tid >> 5;
    int v = s;
#pragma unroll
    for (int o = 1; o < 32; o <<= 1) {
        int t = __shfl_up_sync(0xffffffffu, v, o);
        if (lane >= o) v += t;
    }
    if (lane == 31) wsum[warp] = v;
    __syncthreads();
    if (warp == 0) {
        int w = wsum[lane];
#pragma unroll
        for (int o = 1; o < 32; o <<= 1) {
            int t = __shfl_up_sync(0xffffffffu, w, o);
            if (lane >= o) w += t;
        }
        wsum[lane] = w;
    }
    __syncthreads();
    int excl = v - s + (warp ? wsum[warp - 1] : 0);
    int run = excl;
    for (int i = 0; i < CH; i++) {
        int idx = start + i;
        if (idx < n) { g_rowptr[idx] = run; g_cursor[idx] = run; run += g_deg[idx]; }
    }
    if (tid == 1023) g_rowptr[n] = nE;
}
__global__ void fill_kernel(const void* __restrict__ eidx, int nE) {
    int e = blockIdx.x * blockDim.x + threadIdx.x;
    if (e < nE) {
        int d = edge_at(eidx, 1, e);
        int pos = atomicAdd(&g_cursor[d], 1);
        g_col[pos] = edge_at(eidx, 0, e);
    }
}

// ---------------- x fp32 -> fp16 into stage dstage cols [0, ncols) ----------------
__global__ void conv_A(const float* __restrict__ src, int dstage, int ncols, int M) {
    int nq = ncols >> 2;
    int i = blockIdx.x * blockDim.x + threadIdx.x;
    if (i >= M * nq) return;
    int row = i / nq;
    int c = (i - row * nq) * 4;
    float4 v = *(const float4*)(src + (size_t)row * ncols + c);
    size_t o = (size_t)dstage * NNODES * LDA + (size_t)row * LDA + c;
    __half2* p = (__half2*)(g_act + o);
    p[0] = __floats2half2_rn(v.x, v.y);
    p[1] = __floats2half2_rn(v.z, v.w);
}

// W: fp32 [K, 512] -> transposed hi/lo fp16 [512, K] at region offset woff
__global__ void conv_W(const float* __restrict__ W, int K, int woff) {
    __shared__ float tile[32][33];
    int n0 = blockIdx.x * 32, k0 = blockIdx.y * 32;
    int tx = threadIdx.x, ty = threadIdx.y;        // (32, 8)
    for (int i = ty; i < 32; i += 8)
        tile[i][tx] = W[(size_t)(k0 + i) * HID + n0 + tx];
    __syncthreads();
    for (int i = ty; i < 32; i += 8) {
        float v = tile[tx][i];                      // = W[k0+tx][n0+i]
        __half h = __float2half_rn(v);
        __half l = __float2half_rn(v - __half2float(h));
        size_t o = (size_t)woff + (size_t)(n0 + i) * K + k0 + tx;
        g_wh[o] = h; g_wl[o] = l;
    }
}

// ---------------- mma.sync GEMM, fp16 2-pass, 2-stage cp.async ----------------
// Block tile 160x256, BK=64, 256 threads (8 warps, warp tile 80x64).
// grid (2, 63) = 126 CTAs -> single wave on 148 SMs.
// SMEM stage (84KB): A 20K @0 | Wh 32K @20480 | Wl 32K @53248. 2 stages = 168KB.
// dsel: 0/1 = fp16 act stage, 2 = g_m, 3 = fp32 partial g_pacc (no relu).
// accum: add g_pacc into accumulators before relu (for the aggr-half of the update).
#define STG_BYTES 86016
#define GSMEM (2 * STG_BYTES)

__device__ __forceinline__ void load_stage(
    uint32_t st, const __half* __restrict__ A,
    const __half* __restrict__ Wh, const __half* __restrict__ Wl,
    int kb, int m0, int n0, int K, int M, int tid)
{
#pragma unroll
    for (int t = 0; t < 5; t++) {                 // A: 160 rows x 64 fp16
        int i = tid + t * 256;
        int row = i >> 3, grp = i & 7;
        int gr = m0 + row; if (gr >= M) gr = M - 1;
        size_t off = (size_t)gr * LDA + kb * 64 + grp * 8;
        CP16(st + SWZ128(row * 128 + grp * 16), (const char*)(A + off));
    }
#pragma unroll
    for (int t = 0; t < 8; t++) {                 // W: 256 rows x 64, hi+lo
        int i = tid + t * 256;
        int row = i >> 3, grp = i & 7;
        size_t off = (size_t)(n0 + row) * K + kb * 64 + grp * 8;
        uint32_t sw = SWZ128(row * 128 + grp * 16);
        CP16(st + 20480 + sw, (const char*)(Wh + off));
        CP16(st + 53248 + sw, (const char*)(Wl + off));
    }
}

__global__ void __launch_bounds__(256, 1)
gemm_mma(int asel, int aoff, int K, int woff, const float* __restrict__ bias,
         int dsel, int accum, int M, int doRelu)
{
    extern __shared__ char smem[];
    uint32_t sb = smem_u32(smem);
    const __half* A  = g_act + (size_t)asel * NNODES * LDA + aoff;
    const __half* Wh = g_wh + woff;
    const __half* Wl = g_wl + woff;
    __half* D = nullptr;
    int dstride = HID;
    if (dsel == 2) { D = g_m; dstride = HID; }
    else if (dsel <= 1) { D = g_act + (size_t)dsel * NNODES * LDA; dstride = LDA; }

    int tid = threadIdx.x, lane = tid & 31, wid = tid >> 5;
    int warp_m = wid & 1, warp_n = wid >> 1;      // 2 x 4 warps -> 160 x 256
    int m0 = blockIdx.y * 160, n0 = blockIdx.x * 256;

    float c[5][8][4];
#pragma unroll
    for (int mt = 0; mt < 5; mt++)
#pragma unroll
        for (int nt = 0; nt < 8; nt++)
#pragma unroll
            for (int j = 0; j < 4; j++) c[mt][nt][j] = 0.f;

    const int q = lane >> 3, li = lane & 7;
    int NKB = K >> 6;

    load_stage(sb, A, Wh, Wl, 0, m0, n0, K, M, tid);
    CP_COMMIT();

    for (int kb = 0; kb < NKB; kb++) {
        if (kb + 1 < NKB) {
            load_stage(sb + ((kb + 1) & 1) * STG_BYTES, A, Wh, Wl, kb + 1, m0, n0, K, M, tid);
            CP_COMMIT();
            CP_WAIT1();
        } else {
            CP_WAIT0();
        }
        __syncthreads();

        uint32_t st = sb + (kb & 1) * STG_BYTES;
#pragma unroll
        for (int s = 0; s < 4; s++) {
            uint32_t a[5][4], bh[8][2], bl[8][2];
#pragma unroll
            for (int mt = 0; mt < 5; mt++) {
                int row = warp_m * 80 + mt * 16 + ((q & 1) << 3) + li;
                int grp = s * 2 + (q >> 1);
                LDSM4(a[mt], st + SWZ128(row * 128 + grp * 16));
            }
#pragma unroll
            for (int np = 0; np < 4; np++) {
                int nrow = warp_n * 64 + np * 16 + ((q >> 1) << 3) + li;
                int grp = s * 2 + (q & 1);
                uint32_t bd = st + 20480 + SWZ128(nrow * 128 + grp * 16);
                uint32_t r[4];
                LDSM4(r, bd);
                bh[np*2][0] = r[0]; bh[np*2][1] = r[1];
                bh[np*2+1][0] = r[2]; bh[np*2+1][1] = r[3];
                LDSM4(r, bd + 32768);
                bl[np*2][0] = r[0]; bl[np*2][1] = r[1];
                bl[np*2+1][0] = r[2]; bl[np*2+1][1] = r[3];
            }
#pragma unroll
            for (int mt = 0; mt < 5; mt++)
#pragma unroll
                for (int nt = 0; nt < 8; nt++) {
                    MMA_F16(c[mt][nt], a[mt], bh[nt]);
                    MMA_F16(c[mt][nt], a[mt], bl[nt]);
                }
        }
        __syncthreads();
    }

    // epilogue
    int rlo = lane >> 2;
    int cpos = (lane & 3) * 2;
#pragma unroll
    for (int mt = 0; mt < 5; mt++) {
        int r0 = m0 + warp_m * 80 + mt * 16 + rlo;
#pragma unroll
        for (int nt = 0; nt < 8; nt++) {
            int gc = n0 + warp_n * 64 + nt * 8 + cpos;
            float2 b2 = bias ? *(const float2*)(bias + gc) : make_float2(0.f, 0.f);
            float v0 = c[mt][nt][0] + b2.x, v1 = c[mt][nt][1] + b2.y;
            float v2 = c[mt][nt][2] + b2.x, v3 = c[mt][nt][3] + b2.y;
            if (accum) {
                if (r0 < M) {
                    float2 pa = *(const float2*)(g_pacc + (size_t)r0 * HID + gc);
                    v0 += pa.x; v1 += pa.y;
                }
                if (r0 + 8 < M) {
                    float2 pa = *(const float2*)(g_pacc + (size_t)(r0 + 8) * HID + gc);
                    v2 += pa.x; v3 += pa.y;
                }
            }
            if (doRelu) {
                v0 = fmaxf(v0, 0.f); v1 = fmaxf(v1, 0.f);
                v2 = fmaxf(v2, 0.f); v3 = fmaxf(v3, 0.f);
            }
            if (dsel == 3) {
                if (r0 < M)     *(float2*)(g_pacc + (size_t)r0 * HID + gc) = make_float2(v0, v1);
                if (r0 + 8 < M) *(float2*)(g_pacc + (size_t)(r0 + 8) * HID + gc) = make_float2(v2, v3);
            } else {
                if (r0 < M)
                    *(__half2*)(D + (size_t)r0 * dstride + gc) = __floats2half2_rn(v0, v1);
                if (r0 + 8 < M)
                    *(__half2*)(D + (size_t)(r0 + 8) * dstride + gc) = __floats2half2_rn(v2, v3);
            }
        }
    }
}

// ---------------- aggregation: stage[cur] cols 512..1023 = sum of msg rows ----------------
__global__ void __launch_bounds__(128)
aggregate_kernel(int cur)
{
    int d = blockIdx.x;
    int t = threadIdx.x;
    int c = t * 4;
    float a0 = 0.f, a1 = 0.f, a2 = 0.f, a3 = 0.f;
    int beg = g_rowptr[d], end = g_rowptr[d + 1];
    for (int j = beg; j < end; j++) {
        int s = g_col[j];
        const __half2* p = (const __half2*)(g_m + (size_t)s * HID + c);
        __half2 u0 = p[0], u1 = p[1];
        float2 f0 = __half22float2(u0), f1 = __half22float2(u1);
        a0 += f0.x; a1 += f0.y; a2 += f1.x; a3 += f1.y;
    }
    size_t o = (size_t)cur * NNODES * LDA + (size_t)d * LDA + 512 + c;
    __half2* p = (__half2*)(g_act + o);
    p[0] = __floats2half2_rn(a0, a1);
    p[1] = __floats2half2_rn(a2, a3);
}

// ---------------- output projection ----------------
__global__ void out_kernel(const float* __restrict__ Wout,
                           const float* __restrict__ bout,
                           float* __restrict__ out, int n, int hsel)
{
    int warp = (blockIdx.x * blockDim.x + threadIdx.x) >> 5;
    int lane = threadIdx.x & 31;
    if (warp >= n) return;
    const __half* hr = g_act + (size_t)hsel * NNODES * LDA + (size_t)warp * LDA;
    float s = 0.f;
#pragma unroll 4
    for (int k = lane; k < HID; k += 32)
        s += __half2float(hr[k]) * Wout[k];
#pragma unroll
    for (int o = 16; o; o >>= 1) s += __shfl_down_sync(0xffffffffu, s, o);
    if (lane == 0) out[warp] = s + bout[0];
}

// ---------------- launcher ----------------
extern "C" void kernel_launch(void* const* d_in, const int* in_sizes, int n_in,
                              void* d_out, int out_size)
{
    const float* x     = (const float*)d_in[0];
    const void*  eidx  = d_in[1];
    const float* W_in  = (const float*)d_in[2];
    const float* b_in  = (const float*)d_in[3];
    const float* msg_W = (const float*)d_in[4];
    const float* msg_b = (const float*)d_in[5];
    const float* upd_W = (const float*)d_in[6];
    const float* upd_b = (const float*)d_in[7];
    const float* W_out = (const float*)d_in[8];
    const float* b_out = (const float*)d_in[9];
    float* out = (float*)d_out;

    // streams: s2 = weights + opportunistic upd_h GEMMs (LOW priority), s3 = CSR build
    static cudaStream_t s2 = nullptr, s3 = nullptr;
    static cudaEvent_t eF, wIN, wMSG0, wUPDA0, wMSG1, wUPDA1, e3, eS0, eL1, eUh0, eUh1;
    if (!s2) {
        int leastP, greatestP;
        cudaDeviceGetStreamPriorityRange(&leastP, &greatestP);
        cudaStreamCreateWithPriority(&s2, cudaStreamNonBlocking, leastP);
        cudaStreamCreateWithFlags(&s3, cudaStreamNonBlocking);
        cudaEventCreateWithFlags(&eF,     cudaEventDisableTiming);
        cudaEventCreateWithFlags(&wIN,    cudaEventDisableTiming);
        cudaEventCreateWithFlags(&wMSG0,  cudaEventDisableTiming);
        cudaEventCreateWithFlags(&wUPDA0, cudaEventDisableTiming);
        cudaEventCreateWithFlags(&wMSG1,  cudaEventDisableTiming);
        cudaEventCreateWithFlags(&wUPDA1, cudaEventDisableTiming);
        cudaEventCreateWithFlags(&e3,     cudaEventDisableTiming);
        cudaEventCreateWithFlags(&eS0,    cudaEventDisableTiming);
        cudaEventCreateWithFlags(&eL1,    cudaEventDisableTiming);
        cudaEventCreateWithFlags(&eUh0,   cudaEventDisableTiming);
        cudaEventCreateWithFlags(&eUh1,   cudaEventDisableTiming);
    }

    cudaFuncSetAttribute(gemm_mma, cudaFuncAttributeMaxDynamicSharedMemorySize, GSMEM);

    dim3 ggrid(2, (NNODES + 159) / 160);   // (2, 63) = 126 CTAs, single wave
    const float* uW1 = upd_W + (size_t)1024 * 512;

    // ---- fork side streams ----
    cudaEventRecord(eF, 0);
    cudaStreamWaitEvent(s2, eF, 0);
    cudaStreamWaitEvent(s3, eF, 0);

    // s3: CSR build chain (independent of everything else)
    sniff_kernel<<<1, 256, 0, s3>>>((const unsigned int*)eidx);
    zero_deg_kernel<<<(NNODES + 255) / 256, 256, 0, s3>>>();
    hist_kernel<<<(NEDGES + 255) / 256, 256, 0, s3>>>(eidx, NEDGES);
    scan_kernel<<<1, 1024, 0, s3>>>(NNODES, NEDGES);
    fill_kernel<<<(NEDGES + 255) / 256, 256, 0, s3>>>(eidx, NEDGES);
    cudaEventRecord(e3, s3);

    // s2: all weight conversions, then the two opportunistic upd_h GEMMs
    conv_W<<<dim3(16, INCH / 32), dim3(32, 8), 0, s2>>>(W_in, INCH, WOFF_IN);
    cudaEventRecord(wIN, s2);
    conv_W<<<dim3(16, 16), dim3(32, 8), 0, s2>>>(msg_W, HID, WOFF_MSG0);
    cudaEventRecord(wMSG0, s2);
    conv_W<<<dim3(16, 16), dim3(32, 8), 0, s2>>>(upd_W, HID, WOFF_UPDH0);
    conv_W<<<dim3(16, 16), dim3(32, 8), 0, s2>>>(upd_W + (size_t)512 * 512, HID, WOFF_UPDA0);
    cudaEventRecord(wUPDA0, s2);
    conv_W<<<dim3(16, 16), dim3(32, 8), 0, s2>>>(msg_W + (size_t)512 * 512, HID, WOFF_MSG1);
    cudaEventRecord(wMSG1, s2);
    conv_W<<<dim3(16, 16), dim3(32, 8), 0, s2>>>(uW1, HID, WOFF_UPDH1);
    conv_W<<<dim3(16, 16), dim3(32, 8), 0, s2>>>(uW1 + (size_t)512 * 512, HID, WOFF_UPDA1);
    cudaEventRecord(wUPDA1, s2);

    // main: activation chain
    conv_A<<<(NNODES * (INCH / 4) + 255) / 256, 256>>>(x, 1, INCH, NNODES);
    cudaStreamWaitEvent(0, wIN, 0);
    gemm_mma<<<ggrid, 256, GSMEM>>>(/*a=*/1, 0, INCH, WOFF_IN, b_in, /*d=*/0, 0, NNODES, 1);
    cudaEventRecord(eS0, 0);

    // s2: upd0_h partial = h @ updW[:512] + bias  (runs under msg0/aggr0)
    cudaStreamWaitEvent(s2, eS0, 0);
    gemm_mma<<<ggrid, 256, GSMEM, s2>>>(0, 0, HID, WOFF_UPDH0, upd_b, /*d=*/3, 0, NNODES, 0);
    cudaEventRecord(eUh0, s2);

    // layer 0 critical path
    cudaStreamWaitEvent(0, wMSG0, 0);
    gemm_mma<<<ggrid, 256, GSMEM>>>(0, 0, HID, WOFF_MSG0, msg_b, /*d=*/2, 0, NNODES, 1);
    cudaStreamWaitEvent(0, e3, 0);
    aggregate_kernel<<<NNODES, 128>>>(0);
    cudaStreamWaitEvent(0, eUh0, 0);
    cudaStreamWaitEvent(0, wUPDA0, 0);
    gemm_mma<<<ggrid, 256, GSMEM>>>(0, 512, HID, WOFF_UPDA0, nullptr, /*d=*/1, /*accum=*/1, NNODES, 1);
    cudaEventRecord(eL1, 0);

    // s2: upd1_h partial (runs under msg1/aggr1)
    cudaStreamWaitEvent(s2, eL1, 0);
    gemm_mma<<<ggrid, 256, GSMEM, s2>>>(1, 0, HID, WOFF_UPDH1, upd_b + HID, /*d=*/3, 0, NNODES, 0);
    cudaEventRecord(eUh1, s2);

    // layer 1 critical path
    cudaStreamWaitEvent(0, wMSG1, 0);
    gemm_mma<<<ggrid, 256, GSMEM>>>(1, 0, HID, WOFF_MSG1, msg_b + HID, /*d=*/2, 0, NNODES, 1);
    aggregate_kernel<<<NNODES, 128>>>(1);
    cudaStreamWaitEvent(0, eUh1, 0);
    cudaStreamWaitEvent(0, wUPDA1, 0);
    gemm_mma<<<ggrid, 256, GSMEM>>>(1, 512, HID, WOFF_UPDA1, nullptr, /*d=*/0, /*accum=*/1, NNODES, 1);

    out_kernel<<<(NNODES * 32 + 255) / 256, 256>>>(W_out, b_out, out, NNODES, 0);
}

// round 15
// speedup vs baseline: 1.5657x; 1.5657x over previous
#include <cuda_runtime.h>
#include <cuda_fp16.h>
#include <cstdint>

#define NNODES 10000
#define NEDGES 160000
#define INCH   256
#define HID    512
#define LDA    1024          // activation staging row stride (fp16 elems)

// weight region offsets within g_wh (elems): [N=512, K] transposed per GEMM
#define WOFF_IN   0
#define WOFF_MSG0 (256 * 512)
#define WOFF_UPD0 (WOFF_MSG0 + 512 * 512)
#define WOFF_MSG1 (WOFF_UPD0 + 1024 * 512)
#define WOFF_UPD1 (WOFF_MSG1 + 512 * 512)
#define WTOTAL    (WOFF_UPD1 + 1024 * 512)

// ---------------- device scratch (referenced ONLY from device code) ----------------
__device__ __half g_act[2 * NNODES * LDA];
__device__ __half g_m  [NNODES * HID];
__device__ __half g_wh [WTOTAL];
__device__ int   g_deg   [NNODES];
__device__ int   g_rowptr[NNODES + 1];
__device__ int   g_cursor[NNODES];
__device__ int   g_col   [NEDGES];
__device__ int   g_is64;

__device__ __forceinline__ uint32_t smem_u32(const void* p) {
    uint32_t a;
    asm("{ .reg .u64 t; cvta.to.shared.u64 t, %1; cvt.u32.u64 %0, t; }" : "=r"(a) : "l"(p));
    return a;
}
#define SWZ128(o) ((o) ^ (((o) >> 3) & 0x70))

#define LDSM4(r, addr)                                                        \
    asm volatile("ldmatrix.sync.aligned.m8n8.x4.shared.b16 {%0,%1,%2,%3}, [%4];" \
        : "=r"((r)[0]), "=r"((r)[1]), "=r"((r)[2]), "=r"((r)[3]) : "r"(addr))

#define MMA_F16(d, a, b)                                                      \
    asm volatile("mma.sync.aligned.m16n8k16.row.col.f32.f16.f16.f32 "         \
        "{%0,%1,%2,%3}, {%4,%5,%6,%7}, {%8,%9}, {%0,%1,%2,%3};"               \
        : "+f"((d)[0]), "+f"((d)[1]), "+f"((d)[2]), "+f"((d)[3])              \
        : "r"((a)[0]), "r"((a)[1]), "r"((a)[2]), "r"((a)[3]),                 \
          "r"((b)[0]), "r"((b)[1]))

#define CP16(sa, gp)  asm volatile("cp.async.cg.shared.global [%0], [%1], 16;" :: "r"(sa), "l"(gp))
#define CP_COMMIT()   asm volatile("cp.async.commit_group;" ::: "memory")
#define CP_WAIT0()    asm volatile("cp.async.wait_group 0;" ::: "memory")
#define CP_WAIT1()    asm volatile("cp.async.wait_group 1;" ::: "memory")

// ---------------- edge index (dtype-robust) ----------------
__device__ __forceinline__ int edge_at(const void* p, int which, int e) {
    long long v;
    if (g_is64) v = ((const long long*)p)[(size_t)which * NEDGES + e];
    else        v = ((const int*)p)[(size_t)which * NEDGES + e];
    int iv = (int)v;
    if (iv < 0) iv = 0;
    if (iv >= NNODES) iv = NNODES - 1;
    return iv;
}

__global__ void sniff_kernel(const unsigned int* __restrict__ w) {
    __shared__ int nz;
    if (threadIdx.x == 0) nz = 0;
    __syncthreads();
    int c = 0;
    for (int i = threadIdx.x; i < 2048; i += blockDim.x)
        if (w[2 * i + 1] != 0u) c++;
    if (c) atomicAdd(&nz, c);
    __syncthreads();
    if (threadIdx.x == 0) g_is64 = (nz == 0) ? 1 : 0;
}

// ---------------- CSR build ----------------
__global__ void zero_deg_kernel() {
    int i = blockIdx.x * blockDim.x + threadIdx.x;
    if (i < NNODES) g_deg[i] = 0;
}
__global__ void hist_kernel(const void* __restrict__ eidx, int nE) {
    int e = blockIdx.x * blockDim.x + threadIdx.x;
    if (e < nE) atomicAdd(&g_deg[edge_at(eidx, 1, e)], 1);
}
__global__ void scan_kernel(int n, int nE) {
    __shared__ int wsum[32];
    int tid = threadIdx.x;                 // 1024 threads
    const int CH = (n + 1023) / 1024;
    int start = tid * CH;
    int s = 0;
    for (int i = 0; i < CH; i++) {
        int idx = start + i;
        if (idx < n) s += g_deg[idx];
    }
    int lane = tid & 31, warp = tid >> 5;
    int v = s;
#pragma unroll
    for (int o = 1; o < 32; o <<= 1) {
        int t = __shfl_up_sync(0xffffffffu, v, o);
        if (lane >= o) v += t;
    }
    if (lane == 31) wsum[warp] = v;
    __syncthreads();
    if (warp == 0) {
        int w = wsum[lane];
#pragma unroll
        for (int o = 1; o < 32; o <<= 1) {
            int t = __shfl_up_sync(0xffffffffu, w, o);
            if (lane >= o) w += t;
        }
        wsum[lane] = w;
    }
    __syncthreads();
    int excl = v - s + (warp ? wsum[warp - 1] : 0);
    int run = excl;
    for (int i = 0; i < CH; i++) {
        int idx = start + i;
        if (idx < n) { g_rowptr[idx] = run; g_cursor[idx] = run; run += g_deg[idx]; }
    }
    if (tid == 1023) g_rowptr[n] = nE;
}
__global__ void fill_kernel(const void* __restrict__ eidx, int nE) {
    int e = blockIdx.x * blockDim.x + threadIdx.x;
    if (e < nE) {
        int d = edge_at(eidx, 1, e);
        int pos = atomicAdd(&g_cursor[d], 1);
        g_col[pos] = edge_at(eidx, 0, e);
    }
}

// ---------------- x fp32 -> fp16 into stage dstage cols [0, ncols) ----------------
__global__ void conv_A(const float* __restrict__ src, int dstage, int ncols, int M) {
    int nq = ncols >> 2;
    int i = blockIdx.x * blockDim.x + threadIdx.x;
    if (i >= M * nq) return;
    int row = i / nq;
    int c = (i - row * nq) * 4;
    float4 v = *(const float4*)(src + (size_t)row * ncols + c);
    size_t o = (size_t)dstage * NNODES * LDA + (size_t)row * LDA + c;
    __half2* p = (__half2*)(g_act + o);
    p[0] = __floats2half2_rn(v.x, v.y);
    p[1] = __floats2half2_rn(v.z, v.w);
}

// W: fp32 [K, 512] -> transposed fp16 [512, K] at region offset woff
__global__ void conv_W(const float* __restrict__ W, int K, int woff) {
    __shared__ float tile[32][33];
    int n0 = blockIdx.x * 32, k0 = blockIdx.y * 32;
    int tx = threadIdx.x, ty = threadIdx.y;        // (32, 8)
    for (int i = ty; i < 32; i += 8)
        tile[i][tx] = W[(size_t)(k0 + i) * HID + n0 + tx];
    __syncthreads();
    for (int i = ty; i < 32; i += 8) {
        float v = tile[tx][i];                      // = W[k0+tx][n0+i]
        size_t o = (size_t)woff + (size_t)(n0 + i) * K + k0 + tx;
        g_wh[o] = __float2half_rn(v);
    }
}

// ---------------- mma.sync GEMM, single-pass fp16, 2-stage cp.async ----------------
// Block tile 160x256, BK=64, 256 threads (8 warps, warp tile 80x64).
// grid (2, 63) = 126 CTAs -> single wave on 148 SMs.
// SMEM stage (52KB): A 20K @0 | W 32K @20480. 2 stages = 104KB.
#define STG_BYTES 53248
#define GSMEM (2 * STG_BYTES)

__device__ __forceinline__ void load_stage(
    uint32_t st, const __half* __restrict__ A, const __half* __restrict__ Wh,
    int kb, int m0, int n0, int K, int M, int tid)
{
#pragma unroll
    for (int t = 0; t < 5; t++) {                 // A: 160 rows x 64 fp16
        int i = tid + t * 256;
        int row = i >> 3, grp = i & 7;
        int gr = m0 + row; if (gr >= M) gr = M - 1;
        size_t off = (size_t)gr * LDA + kb * 64 + grp * 8;
        CP16(st + SWZ128(row * 128 + grp * 16), (const char*)(A + off));
    }
#pragma unroll
    for (int t = 0; t < 8; t++) {                 // W: 256 rows x 64 fp16
        int i = tid + t * 256;
        int row = i >> 3, grp = i & 7;
        size_t off = (size_t)(n0 + row) * K + kb * 64 + grp * 8;
        CP16(st + 20480 + SWZ128(row * 128 + grp * 16), (const char*)(Wh + off));
    }
}

__global__ void __launch_bounds__(256, 1)
gemm_mma(int asel, int K, int woff, const float* __restrict__ bias,
         int dsel, int M, int doRelu)
{
    extern __shared__ char smem[];
    uint32_t sb = smem_u32(smem);
    const __half* A  = g_act + (size_t)asel * NNODES * LDA;
    const __half* Wh = g_wh + woff;
    __half* D;
    int dstride;
    if (dsel == 2) { D = g_m; dstride = HID; }
    else { D = g_act + (size_t)dsel * NNODES * LDA; dstride = LDA; }

    int tid = threadIdx.x, lane = tid & 31, wid = tid >> 5;
    int warp_m = wid & 1, warp_n = wid >> 1;      // 2 x 4 warps -> 160 x 256
    int m0 = blockIdx.y * 160, n0 = blockIdx.x * 256;

    float c[5][8][4];
#pragma unroll
    for (int mt = 0; mt < 5; mt++)
#pragma unroll
        for (int nt = 0; nt < 8; nt++)
#pragma unroll
            for (int j = 0; j < 4; j++) c[mt][nt][j] = 0.f;

    const int q = lane >> 3, li = lane & 7;
    int NKB = K >> 6;

    load_stage(sb, A, Wh, 0, m0, n0, K, M, tid);
    CP_COMMIT();

    for (int kb = 0; kb < NKB; kb++) {
        if (kb + 1 < NKB) {
            load_stage(sb + ((kb + 1) & 1) * STG_BYTES, A, Wh, kb + 1, m0, n0, K, M, tid);
            CP_COMMIT();
            CP_WAIT1();
        } else {
            CP_WAIT0();
        }
        __syncthreads();

        uint32_t st = sb + (kb & 1) * STG_BYTES;
#pragma unroll
        for (int s = 0; s < 4; s++) {
            uint32_t a[5][4], bh[8][2];
#pragma unroll
            for (int mt = 0; mt < 5; mt++) {
                int row = warp_m * 80 + mt * 16 + ((q & 1) << 3) + li;
                int grp = s * 2 + (q >> 1);
                LDSM4(a[mt], st + SWZ128(row * 128 + grp * 16));
            }
#pragma unroll
            for (int np = 0; np < 4; np++) {
                int nrow = warp_n * 64 + np * 16 + ((q >> 1) << 3) + li;
                int grp = s * 2 + (q & 1);
                uint32_t r[4];
                LDSM4(r, st + 20480 + SWZ128(nrow * 128 + grp * 16));
                bh[np*2][0] = r[0]; bh[np*2][1] = r[1];
                bh[np*2+1][0] = r[2]; bh[np*2+1][1] = r[3];
            }
#pragma unroll
            for (int mt = 0; mt < 5; mt++)
#pragma unroll
                for (int nt = 0; nt < 8; nt++)
                    MMA_F16(c[mt][nt], a[mt], bh[nt]);
        }
        __syncthreads();
    }

    // epilogue: bias + relu, fp16 stores to staging
    int rlo = lane >> 2;
    int cpos = (lane & 3) * 2;
#pragma unroll
    for (int mt = 0; mt < 5; mt++) {
        int r0 = m0 + warp_m * 80 + mt * 16 + rlo;
#pragma unroll
        for (int nt = 0; nt < 8; nt++) {
            int gc = n0 + warp_n * 64 + nt * 8 + cpos;
            float2 b2 = *(const float2*)(bias + gc);
            float v0 = c[mt][nt][0] + b2.x, v1 = c[mt][nt][1] + b2.y;
            float v2 = c[mt][nt][2] + b2.x, v3 = c[mt][nt][3] + b2.y;
            if (doRelu) {
                v0 = fmaxf(v0, 0.f); v1 = fmaxf(v1, 0.f);
                v2 = fmaxf(v2, 0.f); v3 = fmaxf(v3, 0.f);
            }
            if (r0 < M)
                *(__half2*)(D + (size_t)r0 * dstride + gc) = __floats2half2_rn(v0, v1);
            if (r0 + 8 < M)
                *(__half2*)(D + (size_t)(r0 + 8) * dstride + gc) = __floats2half2_rn(v2, v3);
        }
    }
}

// ---------------- aggregation: stage[cur] cols 512..1023 = sum of msg rows ----------------
__global__ void __launch_bounds__(128)
aggregate_kernel(int cur)
{
    int d = blockIdx.x;
    int t = threadIdx.x;
    int c = t * 4;
    float a0 = 0.f, a1 = 0.f, a2 = 0.f, a3 = 0.f;
    int beg = g_rowptr[d], end = g_rowptr[d + 1];
    for (int j = beg; j < end; j++) {
        int s = g_col[j];
        const __half2* p = (const __half2*)(g_m + (size_t)s * HID + c);
        __half2 u0 = p[0], u1 = p[1];
        float2 f0 = __half22float2(u0), f1 = __half22float2(u1);
        a0 += f0.x; a1 += f0.y; a2 += f1.x; a3 += f1.y;
    }
    size_t o = (size_t)cur * NNODES * LDA + (size_t)d * LDA + 512 + c;
    __half2* p = (__half2*)(g_act + o);
    p[0] = __floats2half2_rn(a0, a1);
    p[1] = __floats2half2_rn(a2, a3);
}

// ---------------- output projection ----------------
__global__ void out_kernel(const float* __restrict__ Wout,
                           const float* __restrict__ bout,
                           float* __restrict__ out, int n, int hsel)
{
    int warp = (blockIdx.x * blockDim.x + threadIdx.x) >> 5;
    int lane = threadIdx.x & 31;
    if (warp >= n) return;
    const __half* hr = g_act + (size_t)hsel * NNODES * LDA + (size_t)warp * LDA;
    float s = 0.f;
#pragma unroll 4
    for (int k = lane; k < HID; k += 32)
        s += __half2float(hr[k]) * Wout[k];
#pragma unroll
    for (int o = 16; o; o >>= 1) s += __shfl_down_sync(0xffffffffu, s, o);
    if (lane == 0) out[warp] = s + bout[0];
}

// ---------------- launcher ----------------
extern "C" void kernel_launch(void* const* d_in, const int* in_sizes, int n_in,
                              void* d_out, int out_size)
{
    const float* x     = (const float*)d_in[0];
    const void*  eidx  = d_in[1];
    const float* W_in  = (const float*)d_in[2];
    const float* b_in  = (const float*)d_in[3];
    const float* msg_W = (const float*)d_in[4];
    const float* msg_b = (const float*)d_in[5];
    const float* upd_W = (const float*)d_in[6];
    const float* upd_b = (const float*)d_in[7];
    const float* W_out = (const float*)d_in[8];
    const float* b_out = (const float*)d_in[9];
    float* out = (float*)d_out;

    // side streams: s2 = weight conversions, s3 = CSR build
    static cudaStream_t s2 = nullptr, s3 = nullptr;
    static cudaEvent_t eF, e1, e2, e3, e4, e5, e6;
    if (!s2) {
        cudaStreamCreateWithFlags(&s2, cudaStreamNonBlocking);
        cudaStreamCreateWithFlags(&s3, cudaStreamNonBlocking);
        cudaEventCreateWithFlags(&eF, cudaEventDisableTiming);
        cudaEventCreateWithFlags(&e1, cudaEventDisableTiming);
        cudaEventCreateWithFlags(&e2, cudaEventDisableTiming);
        cudaEventCreateWithFlags(&e3, cudaEventDisableTiming);
        cudaEventCreateWithFlags(&e4, cudaEventDisableTiming);
        cudaEventCreateWithFlags(&e5, cudaEventDisableTiming);
        cudaEventCreateWithFlags(&e6, cudaEventDisableTiming);
    }

    cudaFuncSetAttribute(gemm_mma, cudaFuncAttributeMaxDynamicSharedMemorySize, GSMEM);

    dim3 ggrid(2, (NNODES + 159) / 160);   // (2, 63) = 126 CTAs, single wave

    // ---- fork side streams ----
    cudaEventRecord(eF, 0);
    cudaStreamWaitEvent(s2, eF, 0);
    cudaStreamWaitEvent(s3, eF, 0);

    // s3: CSR build chain (independent of weights/activations)
    sniff_kernel<<<1, 256, 0, s3>>>((const unsigned int*)eidx);
    zero_deg_kernel<<<(NNODES + 255) / 256, 256, 0, s3>>>();
    hist_kernel<<<(NEDGES + 255) / 256, 256, 0, s3>>>(eidx, NEDGES);
    scan_kernel<<<1, 1024, 0, s3>>>(NNODES, NEDGES);
    fill_kernel<<<(NEDGES + 255) / 256, 256, 0, s3>>>(eidx, NEDGES);
    cudaEventRecord(e3, s3);

    // s2: weight conversions in consumption order
    conv_W<<<dim3(16, INCH / 32), dim3(32, 8), 0, s2>>>(W_in, INCH, WOFF_IN);
    cudaEventRecord(e1, s2);
    conv_W<<<dim3(16, 16), dim3(32, 8), 0, s2>>>(msg_W, HID, WOFF_MSG0);
    cudaEventRecord(e2, s2);
    conv_W<<<dim3(16, 32), dim3(32, 8), 0, s2>>>(upd_W, 1024, WOFF_UPD0);
    cudaEventRecord(e4, s2);
    conv_W<<<dim3(16, 16), dim3(32, 8), 0, s2>>>(msg_W + (size_t)HID * HID, HID, WOFF_MSG1);
    cudaEventRecord(e5, s2);
    conv_W<<<dim3(16, 32), dim3(32, 8), 0, s2>>>(upd_W + (size_t)2 * HID * HID, 1024, WOFF_UPD1);
    cudaEventRecord(e6, s2);

    // main stream: activation chain
    conv_A<<<(NNODES * (INCH / 4) + 255) / 256, 256>>>(x, 1, INCH, NNODES);
    cudaStreamWaitEvent(0, e1, 0);
    gemm_mma<<<ggrid, 256, GSMEM>>>(/*a=*/1, INCH, WOFF_IN, b_in, /*d=*/0, NNODES, 1);

    // layer 0
    cudaStreamWaitEvent(0, e2, 0);
    gemm_mma<<<ggrid, 256, GSMEM>>>(0, HID, WOFF_MSG0, msg_b, /*d=*/2, NNODES, 1);
    cudaStreamWaitEvent(0, e3, 0);
    aggregate_kernel<<<NNODES, 128>>>(0);
    cudaStreamWaitEvent(0, e4, 0);
    gemm_mma<<<ggrid, 256, GSMEM>>>(0, 1024, WOFF_UPD0, upd_b, /*d=*/1, NNODES, 1);

    // layer 1
    cudaStreamWaitEvent(0, e5, 0);
    gemm_mma<<<ggrid, 256, GSMEM>>>(1, HID, WOFF_MSG1, msg_b + HID, /*d=*/2, NNODES, 1);
    aggregate_kernel<<<NNODES, 128>>>(1);
    cudaStreamWaitEvent(0, e6, 0);
    gemm_mma<<<ggrid, 256, GSMEM>>>(1, 1024, WOFF_UPD1, upd_b + HID, /*d=*/0, NNODES, 1);

    out_kernel<<<(NNODES * 32 + 255) / 256, 256>>>(W_out, b_out, out, NNODES, 0);
}